// round 6
// baseline (speedup 1.0000x reference)
#include <cuda_runtime.h>
#include <cuda_fp16.h>
#include <stdint.h>

#define NODES 50000
#define DD 64
#define EDGES_MAX 800000

// ---------------- scratch (no allocations allowed) ----------------
__device__ __align__(16) __half g_ha[NODES * DD];   // fp16: x@W1[0:64]+b1 (dst half)
__device__ __align__(16) __half g_hb[NODES * DD];   // fp16: x@W1[64:128]  (src half)
__device__ __align__(16) float  g_S[NODES * DD];    // segment-sum of relu(ha[dst]+hb[src])
__device__ __align__(16) float  g_aggr[NODES * DD];
__device__ __align__(16) float  g_hid[NODES * DD];
__device__ __align__(16) float  g_deg[NODES];
__device__ __align__(16) int    g_hist[NODES];      // per-dst edge count
__device__ __align__(16) int    g_cursor[NODES];    // base -> mutated to end by scatter
__device__ __align__(16) int    g_sorted[EDGES_MAX];// src ids grouped by dst
__device__ int g_is64;

// ---------------- edge_index dtype detection ----------------
__global__ void detect_kernel(const void* __restrict__ idx) {
    const int* p = (const int*)idx;
    int is64 = 1;
    for (int i = 0; i < 16; i++) {
        int lo = p[2 * i], hi = p[2 * i + 1];
        if (hi != 0 || lo < 0 || lo >= NODES) is64 = 0;
    }
    g_is64 = is64;
}

__global__ void zero_hist() {
    int i = blockIdx.x * blockDim.x + threadIdx.x;
    if (i < NODES) g_hist[i] = 0;
}

// ---------------- histogram of dst (4 edges/thread) ----------------
__global__ void hist_kernel(const void* __restrict__ eidx, int E) {
    int t = blockIdx.x * blockDim.x + threadIdx.x;
    const int is64 = g_is64;
#pragma unroll
    for (int q = 0; q < 4; q++) {
        int e = t * 4 + q;
        if (e >= E) return;
        int dst = is64 ? (int)__ldg(((const long long*)eidx) + E + e)
                       : __ldg(((const int*)eidx) + E + e);
        atomicAdd(&g_hist[dst], 1);
    }
}

// ---------------- single-block exclusive scan over 50k counters ----------------
// 1024 threads, 50 elements each (covers 51200 >= NODES).
__global__ __launch_bounds__(1024) void scan_kernel() {
    __shared__ int part[1024];
    const int t = threadIdx.x;
    const int PER = 50;
    const int base = t * PER;

    int sum = 0;
#pragma unroll 10
    for (int i = 0; i < PER; i++) {
        int idx = base + i;
        sum += (idx < NODES) ? g_hist[idx] : 0;
    }
    part[t] = sum;
    __syncthreads();
    // Hillis-Steele inclusive scan over 1024 partials
    for (int off = 1; off < 1024; off <<= 1) {
        int v = (t >= off) ? part[t - off] : 0;
        __syncthreads();
        part[t] += v;
        __syncthreads();
    }
    int run = part[t] - sum;  // exclusive prefix of this thread's range
#pragma unroll 10
    for (int i = 0; i < PER; i++) {
        int idx = base + i;
        if (idx < NODES) {
            int c = g_hist[idx];   // L2 hit
            g_cursor[idx] = run;   // base; scatter advances to end
            g_deg[idx] = (float)c;
            run += c;
        }
    }
}

// ---------------- scatter: bin src ids by dst ----------------
__global__ void scatter_kernel(const void* __restrict__ eidx, int E) {
    int e = blockIdx.x * blockDim.x + threadIdx.x;
    if (e >= E) return;
    int src, dst;
    if (g_is64) {
        const long long* p = (const long long*)eidx;
        src = (int)__ldg(p + e);
        dst = (int)__ldg(p + E + e);
    } else {
        const int* p = (const int*)eidx;
        src = __ldg(p + e);
        dst = __ldg(p + E + e);
    }
    int pos = atomicAdd(&g_cursor[dst], 1);
    g_sorted[pos] = src;
}

// ================= WIDE GEMM: [ha|hb] = x @ [W1a|W1b] (+b1 on ha), fp16 out =================
__global__ __launch_bounds__(256) void gemm_wide(
    const float* __restrict__ x, const float* __restrict__ W1,
    const float* __restrict__ b1, int n)
{
    extern __shared__ float sm[];
    float* xT = sm;             // [64][132]
    float* Ws = sm + 64 * 132;  // [64][132]

    const int tid = threadIdx.x;
    const int row0 = blockIdx.x * 128;

    for (int i = tid; i < 2048; i += 256) {
        int kk = i >> 4, c4 = (i & 15) * 4;
        float4 v = *(const float4*)(W1 + kk * 64 + c4);
        int k = kk & 63;
        int cc = (kk < 64) ? c4 : (64 + c4);
        *(float4*)&Ws[k * 132 + cc] = v;
    }
    {
        int r = tid >> 1, ks = (tid & 1) * 32, gr = row0 + r;
#pragma unroll
        for (int q = 0; q < 8; q++) {
            float4 v = make_float4(0.f, 0.f, 0.f, 0.f);
            if (gr < n) v = *(const float4*)(x + (size_t)gr * DD + ks + q * 4);
            int k = ks + q * 4;
            xT[(k + 0) * 132 + r] = v.x;
            xT[(k + 1) * 132 + r] = v.y;
            xT[(k + 2) * 132 + r] = v.z;
            xT[(k + 3) * 132 + r] = v.w;
        }
    }
    __syncthreads();

    const int ty = tid >> 4, tx = tid & 15;
    const int r0 = ty * 8, c0 = tx * 8;

    float acc[8][8] = {};
#pragma unroll 2
    for (int k = 0; k < 64; k++) {
        float a[8], w[8];
        *(float4*)&a[0] = *(const float4*)&xT[k * 132 + r0];
        *(float4*)&a[4] = *(const float4*)&xT[k * 132 + r0 + 4];
        *(float4*)&w[0] = *(const float4*)&Ws[k * 132 + c0];
        *(float4*)&w[4] = *(const float4*)&Ws[k * 132 + c0 + 4];
#pragma unroll
        for (int i = 0; i < 8; i++)
#pragma unroll
            for (int j = 0; j < 8; j++)
                acc[i][j] = fmaf(a[i], w[j], acc[i][j]);
    }

    const bool isA = (c0 < 64);
    float bb[8];
#pragma unroll
    for (int j = 0; j < 8; j++) bb[j] = isA ? b1[c0 + j] : 0.f;

#pragma unroll
    for (int i = 0; i < 8; i++) {
        int gr = row0 + r0 + i;
        if (gr >= n) break;
        union { uint4 u; __half2 h[4]; } cvt;
#pragma unroll
        for (int j = 0; j < 4; j++)
            cvt.h[j] = __floats2half2_rn(acc[i][2 * j] + bb[2 * j],
                                         acc[i][2 * j + 1] + bb[2 * j + 1]);
        __half* dstp = isA ? (g_ha + (size_t)gr * DD + c0)
                           : (g_hb + (size_t)gr * DD + (c0 - 64));
        *(uint4*)dstp = cvt.u;
    }
}

// ================= aggregate: one warp per dst, no atomics =================
// S[dst] = sum over its edges of relu(ha[dst] + hb[src]); lanes own 2 channels.
__global__ __launch_bounds__(256) void aggregate_kernel(int n) {
    const int wid = (blockIdx.x * blockDim.x + threadIdx.x) >> 5;
    if (wid >= n) return;
    const int lane = threadIdx.x & 31;
    const int dst = wid;

    const int end = g_cursor[dst];            // post-scatter: base + cnt
    const int cnt = (int)g_deg[dst];
    const int start = end - cnt;

    const float2 fa = __half22float2(((const __half2*)g_ha)[dst * 32 + lane]);
    float accx = 0.f, accy = 0.f;

    for (int b = start; b < end; b += 32) {
        const int m = min(32, end - b);
        int srcv = 0;
        if (b + lane < end) srcv = g_sorted[b + lane];
        for (int j = 0; j < m; j++) {
            const int src = __shfl_sync(0xffffffffu, srcv, j);
            const float2 fb = __half22float2(
                __ldg(((const __half2*)g_hb) + src * 32 + lane));
            accx += fmaxf(fa.x + fb.x, 0.f);
            accy += fmaxf(fa.y + fb.y, 0.f);
        }
    }
    *(float2*)(g_S + (size_t)dst * DD + 2 * lane) = make_float2(accx, accy);
}

// ================= 64-col GEMM: C = act(A1@W[0] (+A2@W[1]) + bias*rowscale) =================
__global__ __launch_bounds__(256) void gemm64(
    const float* __restrict__ A1, const float* __restrict__ A2,
    const float* __restrict__ W, const float* __restrict__ bias,
    const float* __restrict__ rowscale, float* __restrict__ C,
    int n, int do_relu)
{
    extern __shared__ float sm[];
    float* As = sm;             // [64][264]
    float* Ws = sm + 64 * 264;  // [64][68]

    const int tid = threadIdx.x;
    const int row0 = blockIdx.x * 256;
    const int ty = tid >> 3, tx = tid & 7;
    const int r0 = ty * 8, c0 = tx * 8;

    float acc[8][8] = {};

    const int npass = (A2 != nullptr) ? 2 : 1;
    for (int pass = 0; pass < npass; pass++) {
        const float* A = pass ? A2 : A1;
        const float* Wp = W + pass * DD * DD;
        if (pass) __syncthreads();

        for (int i = tid; i < 1024; i += 256) {
            int k = i >> 4, c4 = (i & 15) * 4;
            *(float4*)&Ws[k * 68 + c4] = *(const float4*)(Wp + k * 64 + c4);
        }
        {
            int rr = tid >> 2, l4 = (tid & 3) * 16;
#pragma unroll
            for (int it = 0; it < 4; it++) {
                int r = rr + it * 64;
                int gr = row0 + r;
#pragma unroll
                for (int q = 0; q < 4; q++) {
                    float4 v = make_float4(0.f, 0.f, 0.f, 0.f);
                    if (gr < n) v = *(const float4*)(A + (size_t)gr * DD + l4 + q * 4);
                    int k = l4 + q * 4;
                    As[(k + 0) * 264 + r] = v.x;
                    As[(k + 1) * 264 + r] = v.y;
                    As[(k + 2) * 264 + r] = v.z;
                    As[(k + 3) * 264 + r] = v.w;
                }
            }
        }
        __syncthreads();

#pragma unroll 2
        for (int k = 0; k < 64; k++) {
            float a[8], w[8];
            *(float4*)&a[0] = *(const float4*)&As[k * 264 + r0];
            *(float4*)&a[4] = *(const float4*)&As[k * 264 + r0 + 4];
            *(float4*)&w[0] = *(const float4*)&Ws[k * 68 + c0];
            *(float4*)&w[4] = *(const float4*)&Ws[k * 68 + c0 + 4];
#pragma unroll
            for (int i = 0; i < 8; i++)
#pragma unroll
                for (int j = 0; j < 8; j++)
                    acc[i][j] = fmaf(a[i], w[j], acc[i][j]);
        }
    }

    float bv[8];
#pragma unroll
    for (int j = 0; j < 8; j++) bv[j] = bias ? bias[c0 + j] : 0.f;

#pragma unroll
    for (int i = 0; i < 8; i++) {
        int gr = row0 + r0 + i;
        if (gr >= n) break;
        const float s = rowscale ? rowscale[gr] : 1.0f;
        float o[8];
#pragma unroll
        for (int j = 0; j < 8; j++) {
            o[j] = acc[i][j] + bv[j] * s;
            if (do_relu) o[j] = fmaxf(o[j], 0.f);
        }
        *(float4*)(C + (size_t)gr * DD + c0) = *(float4*)&o[0];
        *(float4*)(C + (size_t)gr * DD + c0 + 4) = *(float4*)&o[4];
    }
}

// ---------------- launch ----------------
extern "C" void kernel_launch(void* const* d_in, const int* in_sizes, int n_in,
                              void* d_out, int out_size) {
    const float* x   = (const float*)d_in[0];
    const void*  eix = d_in[1];
    const float* W1  = (const float*)d_in[2];
    const float* b1  = (const float*)d_in[3];
    const float* W2  = (const float*)d_in[4];
    const float* b2  = (const float*)d_in[5];
    const float* U1  = (const float*)d_in[6];
    const float* ub1 = (const float*)d_in[7];
    const float* U2  = (const float*)d_in[8];
    const float* ub2 = (const float*)d_in[9];
    float* out = (float*)d_out;

    const int n = in_sizes[0] / DD;   // 50000
    const int E = in_sizes[1] / 2;    // 800000

    float *S, *aggr, *hid, *deg;
    cudaGetSymbolAddress((void**)&S,    g_S);
    cudaGetSymbolAddress((void**)&aggr, g_aggr);
    cudaGetSymbolAddress((void**)&hid,  g_hid);
    cudaGetSymbolAddress((void**)&deg,  g_deg);

    const int WIDE_SMEM = 2 * 64 * 132 * 4;          // 67584 B
    const int G64_SMEM  = (64 * 264 + 64 * 68) * 4;  // 84992 B
    cudaFuncSetAttribute(gemm_wide, cudaFuncAttributeMaxDynamicSharedMemorySize, WIDE_SMEM);
    cudaFuncSetAttribute(gemm64,    cudaFuncAttributeMaxDynamicSharedMemorySize, G64_SMEM);

    const int eb = (E + 255) / 256;

    detect_kernel<<<1, 1>>>(eix);
    zero_hist<<<(NODES + 255) / 256, 256>>>();
    hist_kernel<<<(E / 4 + 255) / 256, 256>>>(eix, E);
    scan_kernel<<<1, 1024>>>();
    scatter_kernel<<<eb, 256>>>(eix, E);

    // ha|hb (fp16) — independent of the sort chain
    gemm_wide<<<(n + 127) / 128, 256, WIDE_SMEM>>>(x, W1, b1, n);

    // atomic-free segment reduction: one warp per node
    aggregate_kernel<<<(n * 32 + 255) / 256, 256>>>(n);

    const int nb = (n + 255) / 256;
    gemm64<<<nb, 256, G64_SMEM>>>(S, nullptr, W2, b2, deg, aggr, n, 0);
    gemm64<<<nb, 256, G64_SMEM>>>(x, aggr, U1, ub1, nullptr, hid, n, 1);
    gemm64<<<nb, 256, G64_SMEM>>>(hid, nullptr, U2, ub2, nullptr, out, n, 0);
}

// round 12
// speedup vs baseline: 1.6805x; 1.6805x over previous
#include <cuda_runtime.h>
#include <cuda_fp16.h>
#include <stdint.h>

#define NODES 50000
#define DD 64
#define CAP 64           // per-node bucket capacity (mean degree 16; overflow path below)
#define OVF_MAX 8192

typedef unsigned long long ull;

// ---------------- scratch (no allocations allowed) ----------------
__device__ __align__(16) __half g_ha[NODES * DD];     // fp16: x@W1[0:64]+b1 (dst half)
__device__ __align__(16) __half g_hb[NODES * DD];     // fp16: x@W1[64:128]  (src half)
__device__ __align__(16) float  g_S[NODES * DD];
__device__ __align__(16) float  g_aggr[NODES * DD];
__device__ __align__(16) float  g_hid[NODES * DD];
__device__ __align__(16) float  g_deg[NODES];
__device__ __align__(16) int    g_cnt[NODES];
__device__ __align__(16) int    g_bkt[NODES * CAP];   // src ids bucketed by dst
__device__ __align__(16) int2   g_ovf[OVF_MAX];       // (src,dst) overflow edges
__device__ int g_ovf_n;
__device__ int g_is64;

// ---------------- FFMA2 helpers (verified correct on sm_103a in R2) ----------------
__device__ __forceinline__ void ffma2(ull& d, ull a, ull b) {
    asm("fma.rn.f32x2 %0, %1, %2, %0;" : "+l"(d) : "l"(a), "l"(b));
}
__device__ __forceinline__ ull pack2(float v) {
    unsigned u = __float_as_uint(v);
    ull r;
    asm("mov.b64 %0, {%1, %1};" : "=l"(r) : "r"(u));
    return r;
}
union F2U { ull u; float2 f; };

// ---------------- edge_index dtype detection ----------------
__global__ void detect_kernel(const void* __restrict__ idx) {
    const int* p = (const int*)idx;
    int is64 = 1;
    for (int i = 0; i < 16; i++) {
        int lo = p[2 * i], hi = p[2 * i + 1];
        if (hi != 0 || lo < 0 || lo >= NODES) is64 = 0;
    }
    g_is64 = is64;
}

__global__ void zero_cnt() {
    int i = blockIdx.x * blockDim.x + threadIdx.x;
    if (i < NODES) g_cnt[i] = 0;
    if (i == 0) g_ovf_n = 0;
}

// ---------------- scatter: bucket src ids by dst (no scan needed) ----------------
__global__ void scatter_kernel(const void* __restrict__ eidx, int E) {
    int e = blockIdx.x * blockDim.x + threadIdx.x;
    if (e >= E) return;
    int src, dst;
    if (g_is64) {
        const long long* p = (const long long*)eidx;
        src = (int)__ldg(p + e);
        dst = (int)__ldg(p + E + e);
    } else {
        const int* p = (const int*)eidx;
        src = __ldg(p + e);
        dst = __ldg(p + E + e);
    }
    int pos = atomicAdd(&g_cnt[dst], 1);
    if (pos < CAP) {
        g_bkt[dst * CAP + pos] = src;
    } else {
        int o = atomicAdd(&g_ovf_n, 1);
        if (o < OVF_MAX) g_ovf[o] = make_int2(src, dst);
    }
}

// ================= WIDE GEMM: [ha|hb] = x @ [W1a|W1b] (+b1 on ha), fp16 out, FFMA2 =================
__global__ __launch_bounds__(256, 2) void gemm_wide(
    const float* __restrict__ x, const float* __restrict__ W1,
    const float* __restrict__ b1, int n)
{
    extern __shared__ float sm[];
    float* xT = sm;             // [64][132]
    float* Ws = sm + 64 * 132;  // [64][132]  cc<64 -> ha cols, cc>=64 -> hb cols

    const int tid = threadIdx.x;
    const int row0 = blockIdx.x * 128;

    for (int i = tid; i < 2048; i += 256) {
        int kk = i >> 4, c4 = (i & 15) * 4;
        float4 v = *(const float4*)(W1 + kk * 64 + c4);
        int k = kk & 63;
        int cc = (kk < 64) ? c4 : (64 + c4);
        *(float4*)&Ws[k * 132 + cc] = v;
    }
    {
        int r = tid >> 1, ks = (tid & 1) * 32, gr = row0 + r;
#pragma unroll
        for (int q = 0; q < 8; q++) {
            float4 v = make_float4(0.f, 0.f, 0.f, 0.f);
            if (gr < n) v = *(const float4*)(x + (size_t)gr * DD + ks + q * 4);
            int k = ks + q * 4;
            xT[(k + 0) * 132 + r] = v.x;
            xT[(k + 1) * 132 + r] = v.y;
            xT[(k + 2) * 132 + r] = v.z;
            xT[(k + 3) * 132 + r] = v.w;
        }
    }
    __syncthreads();

    const int ty = tid >> 4, tx = tid & 15;
    const int r0 = ty * 8, c0 = tx * 8;

    ull acc[8][4];
#pragma unroll
    for (int i = 0; i < 8; i++)
#pragma unroll
        for (int j = 0; j < 4; j++) acc[i][j] = 0ULL;

#pragma unroll 2
    for (int k = 0; k < 64; k++) {
        float a[8];
        *(float4*)&a[0] = *(const float4*)&xT[k * 132 + r0];
        *(float4*)&a[4] = *(const float4*)&xT[k * 132 + r0 + 4];
        ulonglong2 w01 = *(const ulonglong2*)&Ws[k * 132 + c0];
        ulonglong2 w23 = *(const ulonglong2*)&Ws[k * 132 + c0 + 4];
        ull W[4] = {w01.x, w01.y, w23.x, w23.y};
        ull A2[8];
#pragma unroll
        for (int i = 0; i < 8; i++) A2[i] = pack2(a[i]);
#pragma unroll
        for (int i = 0; i < 8; i++)
#pragma unroll
            for (int j = 0; j < 4; j++) ffma2(acc[i][j], A2[i], W[j]);
    }

    const bool isA = (c0 < 64);
    float bb[8];
#pragma unroll
    for (int j = 0; j < 8; j++) bb[j] = isA ? b1[c0 + j] : 0.f;

#pragma unroll
    for (int i = 0; i < 8; i++) {
        int gr = row0 + r0 + i;
        if (gr >= n) break;
        union { uint4 u; __half2 h[4]; } cvt;
#pragma unroll
        for (int j = 0; j < 4; j++) {
            F2U u; u.u = acc[i][j];
            cvt.h[j] = __floats2half2_rn(u.f.x + bb[2 * j], u.f.y + bb[2 * j + 1]);
        }
        __half* dstp = isA ? (g_ha + (size_t)gr * DD + c0)
                           : (g_hb + (size_t)gr * DD + (c0 - 64));
        *(uint4*)dstp = cvt.u;
    }
}

// ================= aggregate: one warp per dst, no atomics =================
__global__ __launch_bounds__(256) void aggregate_kernel(int n) {
    const int wid = (blockIdx.x * blockDim.x + threadIdx.x) >> 5;
    if (wid >= n) return;
    const int lane = threadIdx.x & 31;
    const int dst = wid;

    const int cnt = g_cnt[dst];
    const int m = min(cnt, CAP);
    const int* bp = g_bkt + (size_t)dst * CAP;

    const float2 fa = __half22float2(((const __half2*)g_ha)[dst * 32 + lane]);
    float accx = 0.f, accy = 0.f;

    for (int b = 0; b < m; b += 32) {
        const int mm = min(32, m - b);
        int srcv = 0;
        if (b + lane < m) srcv = __ldg(bp + b + lane);
        for (int j = 0; j < mm; j++) {
            const int src = __shfl_sync(0xffffffffu, srcv, j);
            const float2 fb = __half22float2(
                __ldg(((const __half2*)g_hb) + src * 32 + lane));
            accx += fmaxf(fa.x + fb.x, 0.f);
            accy += fmaxf(fa.y + fb.y, 0.f);
        }
    }
    *(float2*)(g_S + (size_t)dst * DD + 2 * lane) = make_float2(accx, accy);
    if (lane == 0) g_deg[dst] = (float)cnt;
}

// ---------------- overflow fixup (normally 0 edges) ----------------
__global__ void overflow_kernel() {
    const int t = blockIdx.x * blockDim.x + threadIdx.x;
    const int e = t >> 4;
    const int lane = t & 15;
    int nov = min(g_ovf_n, OVF_MAX);
    if (e >= nov) return;
    int2 sd = g_ovf[e];
    const float2 fa = __half22float2(((const __half2*)g_ha)[sd.y * 32 + 2 * lane]);
    const float2 fa2 = __half22float2(((const __half2*)g_ha)[sd.y * 32 + 2 * lane + 1]);
    const float2 fb = __half22float2(((const __half2*)g_hb)[sd.x * 32 + 2 * lane]);
    const float2 fb2 = __half22float2(((const __half2*)g_hb)[sd.x * 32 + 2 * lane + 1]);
    float v0 = fmaxf(fa.x + fb.x, 0.f), v1 = fmaxf(fa.y + fb.y, 0.f);
    float v2 = fmaxf(fa2.x + fb2.x, 0.f), v3 = fmaxf(fa2.y + fb2.y, 0.f);
    float* p = g_S + (size_t)sd.y * DD + lane * 4;
    asm volatile("red.global.add.v4.f32 [%0], {%1, %2, %3, %4};"
                 :: "l"(p), "f"(v0), "f"(v1), "f"(v2), "f"(v3) : "memory");
}

// ================= 64-col GEMM (FFMA2): C = act(A1@W[0] (+A2@W[1]) + bias*rowscale) =================
__global__ __launch_bounds__(256, 2) void gemm64(
    const float* __restrict__ A1, const float* __restrict__ A2,
    const float* __restrict__ W, const float* __restrict__ bias,
    const float* __restrict__ rowscale, float* __restrict__ C,
    int n, int do_relu)
{
    extern __shared__ float sm[];
    float* As = sm;             // [64][264]
    float* Ws = sm + 64 * 264;  // [64][68]

    const int tid = threadIdx.x;
    const int row0 = blockIdx.x * 256;
    const int ty = tid >> 3, tx = tid & 7;
    const int r0 = ty * 8, c0 = tx * 8;

    ull acc[8][4];
#pragma unroll
    for (int i = 0; i < 8; i++)
#pragma unroll
        for (int j = 0; j < 4; j++) acc[i][j] = 0ULL;

    const int npass = (A2 != nullptr) ? 2 : 1;
    for (int pass = 0; pass < npass; pass++) {
        const float* A = pass ? A2 : A1;
        const float* Wp = W + pass * DD * DD;
        if (pass) __syncthreads();

        for (int i = tid; i < 1024; i += 256) {
            int k = i >> 4, c4 = (i & 15) * 4;
            *(float4*)&Ws[k * 68 + c4] = *(const float4*)(Wp + k * 64 + c4);
        }
        {
            int rr = tid >> 2, l4 = (tid & 3) * 16;
#pragma unroll
            for (int it = 0; it < 4; it++) {
                int r = rr + it * 64;
                int gr = row0 + r;
#pragma unroll
                for (int q = 0; q < 4; q++) {
                    float4 v = make_float4(0.f, 0.f, 0.f, 0.f);
                    if (gr < n) v = *(const float4*)(A + (size_t)gr * DD + l4 + q * 4);
                    int k = l4 + q * 4;
                    As[(k + 0) * 264 + r] = v.x;
                    As[(k + 1) * 264 + r] = v.y;
                    As[(k + 2) * 264 + r] = v.z;
                    As[(k + 3) * 264 + r] = v.w;
                }
            }
        }
        __syncthreads();

#pragma unroll 2
        for (int k = 0; k < 64; k++) {
            float a[8];
            *(float4*)&a[0] = *(const float4*)&As[k * 264 + r0];
            *(float4*)&a[4] = *(const float4*)&As[k * 264 + r0 + 4];
            ulonglong2 w01 = *(const ulonglong2*)&Ws[k * 68 + c0];
            ulonglong2 w23 = *(const ulonglong2*)&Ws[k * 68 + c0 + 4];
            ull Wv[4] = {w01.x, w01.y, w23.x, w23.y};
            ull A2r[8];
#pragma unroll
            for (int i = 0; i < 8; i++) A2r[i] = pack2(a[i]);
#pragma unroll
            for (int i = 0; i < 8; i++)
#pragma unroll
                for (int j = 0; j < 4; j++) ffma2(acc[i][j], A2r[i], Wv[j]);
        }
    }

    float bv[8];
#pragma unroll
    for (int j = 0; j < 8; j++) bv[j] = bias ? bias[c0 + j] : 0.f;

#pragma unroll
    for (int i = 0; i < 8; i++) {
        int gr = row0 + r0 + i;
        if (gr >= n) break;
        const float s = rowscale ? rowscale[gr] : 1.0f;
        float o[8];
#pragma unroll
        for (int j = 0; j < 4; j++) {
            F2U u; u.u = acc[i][j];
            o[2 * j]     = u.f.x + bv[2 * j] * s;
            o[2 * j + 1] = u.f.y + bv[2 * j + 1] * s;
        }
        if (do_relu) {
#pragma unroll
            for (int j = 0; j < 8; j++) o[j] = fmaxf(o[j], 0.f);
        }
        *(float4*)(C + (size_t)gr * DD + c0) = *(float4*)&o[0];
        *(float4*)(C + (size_t)gr * DD + c0 + 4) = *(float4*)&o[4];
    }
}

// ---------------- launch ----------------
extern "C" void kernel_launch(void* const* d_in, const int* in_sizes, int n_in,
                              void* d_out, int out_size) {
    const float* x   = (const float*)d_in[0];
    const void*  eix = d_in[1];
    const float* W1  = (const float*)d_in[2];
    const float* b1  = (const float*)d_in[3];
    const float* W2  = (const float*)d_in[4];
    const float* b2  = (const float*)d_in[5];
    const float* U1  = (const float*)d_in[6];
    const float* ub1 = (const float*)d_in[7];
    const float* U2  = (const float*)d_in[8];
    const float* ub2 = (const float*)d_in[9];
    float* out = (float*)d_out;

    const int n = in_sizes[0] / DD;   // 50000
    const int E = in_sizes[1] / 2;    // 800000

    float *S, *aggr, *hid, *deg;
    cudaGetSymbolAddress((void**)&S,    g_S);
    cudaGetSymbolAddress((void**)&aggr, g_aggr);
    cudaGetSymbolAddress((void**)&hid,  g_hid);
    cudaGetSymbolAddress((void**)&deg,  g_deg);

    const int WIDE_SMEM = 2 * 64 * 132 * 4;          // 67584 B
    const int G64_SMEM  = (64 * 264 + 64 * 68) * 4;  // 84992 B
    cudaFuncSetAttribute(gemm_wide, cudaFuncAttributeMaxDynamicSharedMemorySize, WIDE_SMEM);
    cudaFuncSetAttribute(gemm64,    cudaFuncAttributeMaxDynamicSharedMemorySize, G64_SMEM);

    detect_kernel<<<1, 1>>>(eix);
    zero_cnt<<<(NODES + 255) / 256, 256>>>();
    scatter_kernel<<<(E + 255) / 256, 256>>>(eix, E);

    // ha|hb (fp16) — independent of the scatter
    gemm_wide<<<(n + 127) / 128, 256, WIDE_SMEM>>>(x, W1, b1, n);

    // atomic-free segment reduction: one warp per node (also writes deg)
    aggregate_kernel<<<(n * 32 + 255) / 256, 256>>>(n);
    overflow_kernel<<<(OVF_MAX * 16 + 255) / 256, 256>>>();

    const int nb = (n + 255) / 256;
    gemm64<<<nb, 256, G64_SMEM>>>(S, nullptr, W2, b2, deg, aggr, n, 0);
    gemm64<<<nb, 256, G64_SMEM>>>(x, aggr, U1, ub1, nullptr, hid, n, 1);
    gemm64<<<nb, 256, G64_SMEM>>>(hid, nullptr, U2, ub2, nullptr, out, n, 0);
}